// round 4
// baseline (speedup 1.0000x reference)
#include <cuda_runtime.h>

// T=2048, B=4096, P=512, NA=2, 7 fields/row.
#define TT 2048
#define BB 4096
#define NF 7
#define CPB 8              // columns per block
#define SUBT 512           // timesteps per subtile
#define NSUB 4             // TT / SUBT
#define CHUNK 16           // steps per thread-chunk
#define CPS 32             // chunks per subtile (SUBT/CHUNK)
#define THREADS 256        // CPS * CPB
#define PQS 515            // padded smem stride (float2 elements) per column

__device__ __forceinline__ float sigmoidf_(float x) { return 1.0f / (1.0f + expf(-x)); }
__device__ __forceinline__ float softplusf_(float x) { return log1pf(expf(x)); }

// swizzled slot for (chunk j, step i) within a column's SUBT-entry PQ row
__device__ __forceinline__ int pq_slot(int j, int i) {
    return j * CHUNK + ((i + 4 * j) & (CHUNK - 1));
}

__global__ void __launch_bounds__(THREADS, 4)
mvt_fused(const float* __restrict__ inp,
          const float* __restrict__ ar_, const float* __restrict__ br_,
          const float* __restrict__ cr_, const float* __restrict__ dr_,
          const float* __restrict__ gr_,
          float* __restrict__ out)
{
    __shared__ float2 sPQ[CPB][PQS];        // per-step (P,Q), swizzled       (~33 KB)
    __shared__ float  sX[THREADS][8];       // A,Bc,dha,cumB,nhB,tipB,cts_end (8 KB)
    __shared__ float  sEgr0[CPS][CPB];      // egr at chunk entry
    __shared__ float  sCtsE[CPS][CPB];      // cts at chunk entry
    __shared__ float  sCarry[CPB][8];       // 0=egr 1=cum 2=nh 3=tip 4=cts

    const int tid = threadIdx.x;
    const int j   = tid >> 3;               // chunk id 0..31
    const int bl  = tid & 7;                // column-in-block 0..7
    const int c0  = blockIdx.x * CPB;
    const int b   = c0 + bl;

    // per-column params (patch id from x[0, b, 6]); redundant per thread, cheap
    const int   pid   = (int)inp[(size_t)b * NF + 6];
    const float alpha = fminf(fmaxf(sigmoidf_(ar_[pid]), 0.01f), 0.99f);
    const float beta  = fminf(fmaxf(softplusf_(br_[pid]), 0.1f), 10.0f);
    const float c     = fminf(fmaxf(cr_[pid], -10.0f), 10.0f);
    const float depl  = fminf(fmaxf(softplusf_(dr_[pid]), 0.001f), 1.0f);
    const float base  = fminf(fmaxf(softplusf_(gr_[pid]), 0.1f), 20.0f);
    const float l2a   = log2f(1.0f - alpha);
    const float bd    = beta * depl;

    if (j == 0) {
        sCarry[bl][0] = base;  // egr
        sCarry[bl][1] = 0.0f;  // cum
        sCarry[bl][2] = 0.0f;  // nh
        sCarry[bl][3] = 0.0f;  // tip
        sCarry[bl][4] = base;  // cts
    }

    const size_t STR = (size_t)BB * NF;
    float2* __restrict__ o2 = reinterpret_cast<float2*>(out);

    for (int s = 0; s < NSUB; ++s) {
        __syncthreads();   // protects sPQ/sX reuse from previous subtile's sweep

        // ── Phase 1: chunk-local transforms + (P,Q) into smem ──
        {
            const float* rowp = inp + (size_t)(s * SUBT + j * CHUNK) * STR + (size_t)b * NF;
            float A = 1.0f, Bc = 0.0f;
            float dha = 1.0f, cumB = 0.0f, nhB = 0.0f, tipB = 0.0f;
            float cts_loc = 0.0f;   // valid from i>=1; i==0 handled by fixup

#pragma unroll
            for (int i = 0; i < CHUNK; ++i) {
                const float* q = rowp + (size_t)i * STR;
                const float dh = q[0];               // exactly 0.0f or 1.0f
                const float r0 = q[2], r1 = q[3];
                const float hd = q[4], td = q[5];

                const float bh = beta * hd;
                float P;
                if (i == 0) P = c;                                   // + bd*cts_entry later
                else        P = c + fmaf(bd, cts_loc, -(bh * Bc));
                const float Q = -(bh * A);
                sPQ[bl][pq_slot(j, i)] = make_float2(P, Q);

                const float ar  = r0 + r1;
                const float ts  = fmaf(dh, hd - td, td);
                const float av  = exp2f(ts * l2a);                   // (1-alpha)^ts
                const float obs = __fdividef(ar, ts + 1e-8f);

                Bc = fmaf(av, Bc, (1.0f - av) * obs);
                A *= av;
                cumB = (cumB + ar)  * dh;
                nhB  = (nhB + 1.0f) * dh;
                tipB = (tipB + ts)  * dh;
                dha *= dh;
                cts_loc = (dh != 0.0f) ? ar : base;
            }
            sX[tid][0] = A;   sX[tid][1] = Bc;  sX[tid][2] = dha;
            sX[tid][3] = cumB; sX[tid][4] = nhB; sX[tid][5] = tipB;
            sX[tid][6] = cts_loc;
        }
        __syncthreads();

        // ── Phase 2: per-column warp scan over 32 chunk transforms ──
        {
            const int w    = tid >> 5;     // warp = column w (8 warps, 8 columns)
            const int lane = tid & 31;     // lane = chunk id
            const int src  = lane * CPB + w;

            float iA  = sX[src][0], iB  = sX[src][1];
            float idh = sX[src][2], icu = sX[src][3], inh = sX[src][4], iti = sX[src][5];
            const float ctse = sX[src][6];

            const float carry_egr = sCarry[w][0];
            const float carry_cum = sCarry[w][1];
            const float carry_nh  = sCarry[w][2];
            const float carry_tip = sCarry[w][3];
            const float carry_cts = sCarry[w][4];

#pragma unroll
            for (int d = 1; d < 32; d <<= 1) {
                const float pA = __shfl_up_sync(0xFFFFFFFFu, iA, d);
                const float pB = __shfl_up_sync(0xFFFFFFFFu, iB, d);
                const float pd = __shfl_up_sync(0xFFFFFFFFu, idh, d);
                const float pc = __shfl_up_sync(0xFFFFFFFFu, icu, d);
                const float pn = __shfl_up_sync(0xFFFFFFFFu, inh, d);
                const float pt = __shfl_up_sync(0xFFFFFFFFu, iti, d);
                if (lane >= d) {
                    iB  = fmaf(iA, pB, iB);   iA  *= pA;   // compose T_lane ∘ S_prev
                    icu = fmaf(idh, pc, icu);
                    inh = fmaf(idh, pn, inh);
                    iti = fmaf(idh, pt, iti);
                    idh *= pd;
                }
            }

            // entry values = exclusive prefix applied to carries
            const float exA = __shfl_up_sync(0xFFFFFFFFu, iA, 1);
            const float exB = __shfl_up_sync(0xFFFFFFFFu, iB, 1);
            sEgr0[lane][w] = (lane == 0) ? carry_egr : fmaf(exA, carry_egr, exB);
            const float pcts = __shfl_up_sync(0xFFFFFFFFu, ctse, 1);
            sCtsE[lane][w] = (lane == 0) ? carry_cts : pcts;

            if (lane == 31) {
                sCarry[w][0] = fmaf(iA, carry_egr, iB);
                sCarry[w][1] = fmaf(idh, carry_cum, icu);
                sCarry[w][2] = fmaf(idh, carry_nh,  inh);
                sCarry[w][3] = fmaf(idh, carry_tip, iti);
                sCarry[w][4] = ctse;
            }
        }
        __syncthreads();

        // ── Phase 2.5: fix up first-step P with bd * cts_entry ──
        sPQ[bl][pq_slot(j, 0)].x += bd * sCtsE[j][bl];
        __syncthreads();

        // ── Phase 3: coalesced logit sweep ──
#pragma unroll
        for (int k = 0; k < (SUBT * CPB) / THREADS; ++k) {       // 16 iters
            const int lin = k * THREADS + tid;
            const int t   = lin >> 3;
            const int wbl = lin & 7;
            const int jj  = t >> 4, ii = t & 15;
            const float2 pq = sPQ[wbl][pq_slot(jj, ii)];
            const float  e0 = sEgr0[jj][wbl];
            o2[(size_t)(s * SUBT + t) * BB + c0 + wbl] =
                make_float2(fmaf(pq.y, e0, pq.x), 0.0f);
        }
    }

    __syncthreads();
    if (tid < CPB) {
        float* fin = out + (size_t)TT * BB * 2;
        const int bc = c0 + tid;
        fin[bc]           = sCarry[tid][1];  // cum
        fin[BB + bc]      = sCarry[tid][2];  // nh
        fin[2 * BB + bc]  = sCarry[tid][3];  // tip
        fin[3 * BB + bc]  = sCarry[tid][0];  // egr
        fin[4 * BB + bc]  = sCarry[tid][4];  // cts
    }
}

extern "C" void kernel_launch(void* const* d_in, const int* in_sizes, int n_in,
                              void* d_out, int out_size)
{
    (void)in_sizes; (void)n_in; (void)out_size;
    const float* inp  = (const float*)d_in[0];
    const float* araw = (const float*)d_in[1];
    const float* braw = (const float*)d_in[2];
    const float* craw = (const float*)d_in[3];
    const float* draw = (const float*)d_in[4];
    const float* graw = (const float*)d_in[5];

    mvt_fused<<<BB / CPB, THREADS>>>(inp, araw, braw, craw, draw, graw, (float*)d_out);
}

// round 5
// speedup vs baseline: 1.3305x; 1.3305x over previous
#include <cuda_runtime.h>

// T=2048, B=4096, P=512, NA=2, 7 fields/row.
#define TT 2048
#define BB 4096
#define NF 7
#define CC 32          // chunks per column
#define LL 64          // TT / CC
#define CB (CC * BB)   // 131072 chunk-column pairs

// Scratch (device globals: no runtime allocation allowed)
__device__ float2 g_PQ[(size_t)TT * BB];      // per-step (P, Q): logit = P + Q*egr_start  (64 MB)
__device__ float  g_tf[7 * CB];               // per-chunk transforms: [k][j*BB+b]
                                              // k: 0=egrA 1=egrB 2=dhprod 3=cumB 4=nhB 5=tipB 6=cts_end
__device__ float  g_egr0[CB];                 // egr at chunk start, per (j,b)

__device__ __forceinline__ float sigmoidf_(float x) { return 1.0f / (1.0f + expf(-x)); }
__device__ __forceinline__ float softplusf_(float x) { return log1pf(expf(x)); }

struct Params { float alpha, beta, c, depl, base, l2a; };

__device__ __forceinline__ Params load_params(
    const float* __restrict__ inp, int b,
    const float* __restrict__ ar_, const float* __restrict__ br_,
    const float* __restrict__ cr_, const float* __restrict__ dr_,
    const float* __restrict__ gr_)
{
    Params pr;
    const int pid = (int)inp[(size_t)b * NF + 6];
    pr.alpha = fminf(fmaxf(sigmoidf_(ar_[pid]), 0.01f), 0.99f);
    pr.beta  = fminf(fmaxf(softplusf_(br_[pid]), 0.1f), 10.0f);
    pr.c     = fminf(fmaxf(cr_[pid], -10.0f), 10.0f);
    pr.depl  = fminf(fmaxf(softplusf_(dr_[pid]), 0.001f), 1.0f);
    pr.base  = fminf(fmaxf(softplusf_(gr_[pid]), 0.1f), 20.0f);
    pr.l2a   = log2f(1.0f - pr.alpha);
    return pr;
}

// ───────── Pass 1: per-(b,chunk) local affine composition + (P,Q) emission ─────────
// (unchanged from R2 — measured at the HBM mixed r/w ceiling)
__global__ void __launch_bounds__(256)
mvt_pass1(const float* __restrict__ inp,
          const float* __restrict__ ar_, const float* __restrict__ br_,
          const float* __restrict__ cr_, const float* __restrict__ dr_,
          const float* __restrict__ gr_)
{
    const int tid = blockIdx.x * 256 + threadIdx.x;   // tid = j*BB + b
    const int j = tid >> 12;                          // / 4096
    const int b = tid & (BB - 1);

    const Params pr = load_params(inp, b, ar_, br_, cr_, dr_, gr_);
    const float bd = pr.beta * pr.depl;

    const float*  p   = inp + (size_t)b * NF;
    const size_t  STR = (size_t)BB * NF;
    const int     t0  = j * LL;

    // cts at entry of this chunk: function of input row t0-1 only (or base for j==0)
    float cts_prev = pr.base;
    if (j != 0) {
        const float* q = p + (size_t)(t0 - 1) * STR;
        const float dh = q[0];
        const float ar = q[2] + q[3];
        cts_prev = (dh != 0.0f) ? ar : pr.base;
    }

    float A = 1.0f, Bc = 0.0f;                 // egr prefix: egr_{t-1} = A*egr_start + Bc
    float dha = 1.0f, cumB = 0.0f, nhB = 0.0f, tipB = 0.0f;

    float2* __restrict__ pq = g_PQ + b;

#pragma unroll 4
    for (int t = t0; t < t0 + LL; ++t) {
        const float* q = p + (size_t)t * STR;
        const float dh = q[0];                 // exactly 0.0f or 1.0f
        const float r0 = q[2], r1 = q[3];
        const float hd = q[4], td = q[5];

        // logit_t = P + Q * egr_start
        const float bh = pr.beta * hd;
        const float P  = pr.c + fmaf(bd, cts_prev, -(bh * Bc));
        const float Q  = -(bh * A);
        pq[(size_t)t * BB] = make_float2(P, Q);

        // step update (all input-only coefficients)
        const float ar  = r0 + r1;
        const float ts  = fmaf(dh, hd - td, td);
        const float av  = exp2f(ts * pr.l2a);         // (1-alpha)^ts
        const float obs = __fdividef(ar, ts + 1e-8f);

        Bc = fmaf(av, Bc, (1.0f - av) * obs);         // egr prefix compose
        A *= av;

        cumB = (cumB + ar)  * dh;
        nhB  = (nhB + 1.0f) * dh;
        tipB = (tipB + ts)  * dh;
        dha *= dh;
        cts_prev = (dh != 0.0f) ? ar : pr.base;
    }

    g_tf[0 * CB + tid] = A;
    g_tf[1 * CB + tid] = Bc;
    g_tf[2 * CB + tid] = dha;
    g_tf[3 * CB + tid] = cumB;
    g_tf[4 * CB + tid] = nhB;
    g_tf[5 * CB + tid] = tipB;
    g_tf[6 * CB + tid] = cts_prev;            // cts at end of chunk
}

// ───────── Pass 2: warp-per-column Kogge–Stone scan over 32 chunk transforms ─────────
// 512 blocks × 8 warps = 4096 warps; lane = chunk id, all loads coalesced + independent.
__global__ void __launch_bounds__(256)
mvt_pass2(const float* __restrict__ inp,
          const float* __restrict__ ar_, const float* __restrict__ br_,
          const float* __restrict__ cr_, const float* __restrict__ dr_,
          const float* __restrict__ gr_,
          float* __restrict__ out)
{
    const int w    = threadIdx.x >> 5;              // warp -> column within block
    const int lane = threadIdx.x & 31;              // lane -> chunk id
    const int b    = blockIdx.x * 8 + w;
    const int idx  = lane * BB + b;

    // 7 independent coalesced loads (MLP=7), no dependent chain
    float iA   = g_tf[0 * CB + idx];
    float iB   = g_tf[1 * CB + idx];
    float idh  = g_tf[2 * CB + idx];
    float icu  = g_tf[3 * CB + idx];
    float inh  = g_tf[4 * CB + idx];
    float iti  = g_tf[5 * CB + idx];
    const float ctsL = g_tf[6 * CB + idx];

    const Params pr = load_params(inp, b, ar_, br_, cr_, dr_, gr_);

#pragma unroll
    for (int d = 1; d < 32; d <<= 1) {
        const float pA = __shfl_up_sync(0xFFFFFFFFu, iA, d);
        const float pB = __shfl_up_sync(0xFFFFFFFFu, iB, d);
        const float pd = __shfl_up_sync(0xFFFFFFFFu, idh, d);
        const float pc = __shfl_up_sync(0xFFFFFFFFu, icu, d);
        const float pn = __shfl_up_sync(0xFFFFFFFFu, inh, d);
        const float pt = __shfl_up_sync(0xFFFFFFFFu, iti, d);
        if (lane >= d) {
            iB  = fmaf(iA, pB, iB);   iA  *= pA;    // affine compose (egr)
            icu = fmaf(idh, pc, icu);
            inh = fmaf(idh, pn, inh);
            iti = fmaf(idh, pt, iti);
            idh *= pd;
        }
    }

    // exclusive prefix applied to initial carry (egr_init = base)
    const float exA = __shfl_up_sync(0xFFFFFFFFu, iA, 1);
    const float exB = __shfl_up_sync(0xFFFFFFFFu, iB, 1);
    g_egr0[idx] = (lane == 0) ? pr.base : fmaf(exA, pr.base, exB);

    if (lane == 31) {
        float* fin = out + (size_t)TT * BB * 2;
        fin[b]          = icu;                        // cum  (carry_cum = 0)
        fin[BB + b]     = inh;                        // nh   (carry = 0)
        fin[2 * BB + b] = iti;                        // tip  (carry = 0)
        fin[3 * BB + b] = fmaf(iA, pr.base, iB);      // egr
        fin[4 * BB + b] = ctsL;                       // cts = last chunk's end value
    }
}

// ───────── Pass 3: vectorized map — two logits per thread via float4 ─────────
__global__ void __launch_bounds__(256)
mvt_pass3(float* __restrict__ out)
{
    const size_t i2 = (size_t)blockIdx.x * 256 + threadIdx.x;  // pair index
    const size_t i  = i2 * 2;                                  // i = t*BB + b (b even)
    const int b = (int)(i & (BB - 1));
    const int t = (int)(i >> 12);
    const int j = t >> 6;                                      // chunk id

    const float4 pq2 = reinterpret_cast<const float4*>(g_PQ)[i2];
    const float  e0a = g_egr0[j * BB + b];
    const float  e0b = g_egr0[j * BB + b + 1];

    reinterpret_cast<float4*>(out)[i2] =
        make_float4(fmaf(pq2.y, e0a, pq2.x), 0.0f,
                    fmaf(pq2.w, e0b, pq2.z), 0.0f);
}

extern "C" void kernel_launch(void* const* d_in, const int* in_sizes, int n_in,
                              void* d_out, int out_size)
{
    (void)in_sizes; (void)n_in; (void)out_size;
    const float* inp  = (const float*)d_in[0];
    const float* araw = (const float*)d_in[1];
    const float* braw = (const float*)d_in[2];
    const float* craw = (const float*)d_in[3];
    const float* draw = (const float*)d_in[4];
    const float* graw = (const float*)d_in[5];
    float* out = (float*)d_out;

    mvt_pass1<<<CB / 256, 256>>>(inp, araw, braw, craw, draw, graw);
    mvt_pass2<<<BB / 8, 256>>>(inp, araw, braw, craw, draw, graw, out);
    mvt_pass3<<<(unsigned)(((size_t)TT * BB / 2) / 256), 256>>>(out);
}

// round 7
// speedup vs baseline: 1.4804x; 1.1127x over previous
#include <cuda_runtime.h>

// T=2048, B=4096, P=512, NA=2, 7 fields/row.
#define TT 2048
#define BB 4096
#define NF 7
#define CHUNK 32            // timesteps per chunk
#define CC 64               // TT / CHUNK
#define CB (CC * BB)        // 262144 (chunk, column) pairs
#define THREADS 256

// Decoupled-lookback scratch (device globals; flags cleared per launch).
// agg planes 0..5:  A,B (egr affine), dha, cumB, nhB, tipB   (transform of chunk)
// inc planes 6..11: egr,cum,nh,tip inclusive state after chunk (6..9; 10,11 unused)
__device__ float    g_pay[12 * CB];
__device__ unsigned g_flag[CB];      // 0 = none, 1 = aggregate ready, 2 = inclusive ready

__device__ __forceinline__ float sigmoidf_(float x) { return 1.0f / (1.0f + expf(-x)); }
__device__ __forceinline__ float softplusf_(float x) { return log1pf(expf(x)); }

// ── clear flags each launch (graph-replay safe) ──
__global__ void __launch_bounds__(256)
mvt_clear()
{
    reinterpret_cast<uint4*>(g_flag)[blockIdx.x * 256 + threadIdx.x] =
        make_uint4(0, 0, 0, 0);
}

__global__ void __launch_bounds__(THREADS, 3)
mvt_main(const float* __restrict__ inp,
         const float* __restrict__ ar_, const float* __restrict__ br_,
         const float* __restrict__ cr_, const float* __restrict__ dr_,
         const float* __restrict__ gr_,
         float* __restrict__ out)
{
    extern __shared__ float2 sPQ[];           // [CHUNK][THREADS] = 64 KB

    const int tid  = threadIdx.x;
    const int j    = blockIdx.x >> 4;         // chunk id 0..63 (low blocks = low j)
    const int bgrp = blockIdx.x & 15;
    const int b    = bgrp * THREADS + tid;    // column
    const int idx  = j * BB + b;

    // per-column params
    const int   pid   = (int)inp[(size_t)b * NF + 6];
    const float alpha = fminf(fmaxf(sigmoidf_(ar_[pid]), 0.01f), 0.99f);
    const float beta  = fminf(fmaxf(softplusf_(br_[pid]), 0.1f), 10.0f);
    const float c     = fminf(fmaxf(cr_[pid], -10.0f), 10.0f);
    const float depl  = fminf(fmaxf(softplusf_(dr_[pid]), 0.001f), 1.0f);
    const float base  = fminf(fmaxf(softplusf_(gr_[pid]), 0.1f), 20.0f);
    const float l2a   = log2f(1.0f - alpha);
    const float bd    = beta * depl;

    const float*  p   = inp + (size_t)b * NF;
    const size_t  STR = (size_t)BB * NF;
    const int     t0  = j * CHUNK;

    // cts entering this chunk: function of input row t0-1 only (or base for j==0)
    float cts_prev = base;
    if (j != 0) {
        const float* q = p + (size_t)(t0 - 1) * STR;
        cts_prev = (q[0] != 0.0f) ? (q[2] + q[3]) : base;
    }

    // ── Phase A: chunk-local transforms; (P,Q) into smem ──
    float A = 1.0f, Bc = 0.0f;                // egr_{t-1} = A*egr_entry + Bc
    float dha = 1.0f, cumB = 0.0f, nhB = 0.0f, tipB = 0.0f;

#pragma unroll 4
    for (int i = 0; i < CHUNK; ++i) {
        const float* q = p + (size_t)(t0 + i) * STR;
        const float dh = q[0];                // exactly 0.0f or 1.0f
        const float r0 = q[2], r1 = q[3];
        const float hd = q[4], td = q[5];

        const float bh = beta * hd;
        const float P  = c + fmaf(bd, cts_prev, -(bh * Bc));
        const float Q  = -(bh * A);
        sPQ[i * THREADS + tid] = make_float2(P, Q);

        const float ar  = r0 + r1;
        const float ts  = fmaf(dh, hd - td, td);
        const float av  = exp2f(ts * l2a);    // (1-alpha)^ts
        const float obs = __fdividef(ar, ts + 1e-8f);

        Bc = fmaf(av, Bc, (1.0f - av) * obs);
        A *= av;
        cumB = (cumB + ar)  * dh;
        nhB  = (nhB + 1.0f) * dh;
        tipB = (tipB + ts)  * dh;
        dha *= dh;
        cts_prev = (dh != 0.0f) ? ar : base;
    }

    // publish aggregate (payload, fence, release flag=1)
    if (j != 0) {
        g_pay[0 * CB + idx] = A;
        g_pay[1 * CB + idx] = Bc;
        g_pay[2 * CB + idx] = dha;
        g_pay[3 * CB + idx] = cumB;
        g_pay[4 * CB + idx] = nhB;
        g_pay[5 * CB + idx] = tipB;
        __threadfence();
        *((volatile unsigned*)&g_flag[idx]) = 1u;
    }

    // ── Phase B: decoupled lookback with inclusive early-termination ──
    // R = composition of already-folded transforms T_{j-1}..T_{k+1}
    float Ra = 1.0f, Rb = 0.0f;               // egr
    float Rd = 1.0f, Rc = 0.0f, Rn = 0.0f, Rt = 0.0f;
    // entry state of chunk j:
    float egr0 = base, cum0 = 0.0f, nh0 = 0.0f, tip0 = 0.0f;

    for (int k = j - 1; k >= 0; --k) {
        const int kk = k * BB + b;
        unsigned f;
        for (;;) {
            f = *((volatile unsigned*)&g_flag[kk]);
            if (f) break;
            __nanosleep(50);
        }
        __threadfence();                      // acquire: payload after flag
        if (f == 2u) {
            // inclusive state after chunk k: apply R to it, done
            const float Se = *((volatile float*)&g_pay[6 * CB + kk]);
            const float Sc = *((volatile float*)&g_pay[7 * CB + kk]);
            const float Sn = *((volatile float*)&g_pay[8 * CB + kk]);
            const float St = *((volatile float*)&g_pay[9 * CB + kk]);
            egr0 = fmaf(Ra, Se, Rb);
            cum0 = fmaf(Rd, Sc, Rc);
            nh0  = fmaf(Rd, Sn, Rn);
            tip0 = fmaf(Rd, St, Rt);
            break;
        }
        // aggregate only: fold T_k into R, keep walking
        const float TA = *((volatile float*)&g_pay[0 * CB + kk]);
        const float TB = *((volatile float*)&g_pay[1 * CB + kk]);
        const float Td = *((volatile float*)&g_pay[2 * CB + kk]);
        const float Tc = *((volatile float*)&g_pay[3 * CB + kk]);
        const float Tn = *((volatile float*)&g_pay[4 * CB + kk]);
        const float Tt = *((volatile float*)&g_pay[5 * CB + kk]);
        Rb = fmaf(Ra, TB, Rb);  Ra *= TA;     // R = R ∘ T_k
        Rc = fmaf(Rd, Tc, Rc);
        Rn = fmaf(Rd, Tn, Rn);
        Rt = fmaf(Rd, Tt, Rt);
        Rd *= Td;
        if (k == 0) {                          // hit the start: apply R to init state
            egr0 = fmaf(Ra, base, Rb);
            cum0 = Rc; nh0 = Rn; tip0 = Rt;
        }
    }

    // inclusive state after chunk j; publish (flag=2) so successors stop here
    const float egrI = fmaf(A, egr0, Bc);
    const float cumI = fmaf(dha, cum0, cumB);
    const float nhI  = fmaf(dha, nh0,  nhB);
    const float tipI = fmaf(dha, tip0, tipB);
    if (j != CC - 1) {
        g_pay[6 * CB + idx] = egrI;
        g_pay[7 * CB + idx] = cumI;
        g_pay[8 * CB + idx] = nhI;
        g_pay[9 * CB + idx] = tipI;
        __threadfence();
        *((volatile unsigned*)&g_flag[idx]) = 2u;
    }

    // ── Phase C: write logits straight from smem ──
    float2* __restrict__ o2 = reinterpret_cast<float2*>(out) + b;
#pragma unroll 4
    for (int i = 0; i < CHUNK; ++i) {
        const float2 pq = sPQ[i * THREADS + tid];
        o2[(size_t)(t0 + i) * BB] = make_float2(fmaf(pq.y, egr0, pq.x), 0.0f);
    }

    // ── finals: last chunk owns the full-column state ──
    if (j == CC - 1) {
        float* fin = out + (size_t)TT * BB * 2;
        fin[b]          = cumI;
        fin[BB + b]     = nhI;
        fin[2 * BB + b] = tipI;
        fin[3 * BB + b] = egrI;
        fin[4 * BB + b] = cts_prev;           // cts at t = T-1
    }
}

extern "C" void kernel_launch(void* const* d_in, const int* in_sizes, int n_in,
                              void* d_out, int out_size)
{
    (void)in_sizes; (void)n_in; (void)out_size;
    const float* inp  = (const float*)d_in[0];
    const float* araw = (const float*)d_in[1];
    const float* braw = (const float*)d_in[2];
    const float* craw = (const float*)d_in[3];
    const float* draw = (const float*)d_in[4];
    const float* graw = (const float*)d_in[5];

    cudaFuncSetAttribute(mvt_main,
                         cudaFuncAttributeMaxDynamicSharedMemorySize,
                         CHUNK * THREADS * sizeof(float2));

    mvt_clear<<<CB / (256 * 4), 256>>>();
    mvt_main<<<CC * (BB / THREADS), THREADS, CHUNK * THREADS * sizeof(float2)>>>(
        inp, araw, braw, craw, draw, graw, (float*)d_out);
}